// round 15
// baseline (speedup 1.0000x reference)
#include <cuda_runtime.h>
#include <cuda_fp16.h>
#include <cstdint>

#define NODES_TOTAL 100000
#define NNODES      20000
#define TN          50
#define INF         256
#define HIDF        256
#define OUTF        256
#define CATF        512

// Scratch (static __device__ arrays: allocation-free per harness rules)
__device__ __align__(16) __half g_qh[(size_t)NODES_TOTAL * HIDF];  // 51.2 MB
__device__ __align__(16) __half g_cat[(size_t)NNODES * CATF];      // 20.5 MB
__device__ __align__(16) __half g_qw16[INF * HIDF];                // Qw fp16
__device__ __align__(16) __half g_ww16[OUTF * CATF];               // Ww fp16

// ---------------------------------------------------------------------------
// helpers
// ---------------------------------------------------------------------------
__device__ __forceinline__ void mma_f16_f32acc(float c[4], const uint32_t a[4],
                                               uint32_t b0, uint32_t b1) {
    asm volatile("mma.sync.aligned.m16n8k16.row.col.f32.f16.f16.f32 "
                 "{%0,%1,%2,%3}, {%4,%5,%6,%7}, {%8,%9}, {%0,%1,%2,%3};"
                 : "+f"(c[0]), "+f"(c[1]), "+f"(c[2]), "+f"(c[3])
                 : "r"(a[0]), "r"(a[1]), "r"(a[2]), "r"(a[3]), "r"(b0), "r"(b1));
}

__device__ __forceinline__ void ldmatrix_x4(uint32_t r[4], uint32_t saddr) {
    asm volatile("ldmatrix.sync.aligned.m8n8.x4.shared.b16 {%0,%1,%2,%3}, [%4];"
                 : "=r"(r[0]), "=r"(r[1]), "=r"(r[2]), "=r"(r[3]) : "r"(saddr));
}

__device__ __forceinline__ uint32_t pack_h2(float x, float y) {
    __half2 h = __float22half2_rn(make_float2(x, y));
    return *(uint32_t*)&h;
}

__device__ __forceinline__ void cp_async16(void* smem_dst, const void* gmem_src, bool pred) {
    uint32_t saddr = (uint32_t)__cvta_generic_to_shared(smem_dst);
    int sz = pred ? 16 : 0;
    asm volatile("cp.async.cg.shared.global [%0], [%1], 16, %2;"
                 :: "r"(saddr), "l"(gmem_src), "r"(sz));
}
#define CP_COMMIT() asm volatile("cp.async.commit_group;")
#define CP_WAIT0()  asm volatile("cp.async.wait_group 0;")
#define CP_WAIT1()  asm volatile("cp.async.wait_group 1;")

#define SROWH 40   // smem row stride in halves (80B -> conflict-free ldmatrix)

// ---------------------------------------------------------------------------
// k0: one-shot weight conversion fp32 -> fp16 (RN)
// ---------------------------------------------------------------------------
__global__ __launch_bounds__(256) void cvt_weights_kernel(
    const float* __restrict__ Qw, const float* __restrict__ Ww)
{
    const int i = blockIdx.x * 256 + threadIdx.x;
    if (i < 16384) {
        const float4 v = ((const float4*)Qw)[i];
        ((uint2*)g_qw16)[i] = make_uint2(pack_h2(v.x, v.y), pack_h2(v.z, v.w));
    } else if (i < 49152) {
        const int j = i - 16384;
        const float4 v = ((const float4*)Ww)[j];
        ((uint2*)g_ww16)[j] = make_uint2(pack_h2(v.x, v.y), pack_h2(v.z, v.w));
    }
}

// ===========================================================================
// GEMM-A half: QH[m0..m0+63, n0..n0+127] = relu( h @ Qw^T + Qb ), fp16 out.
// K=256, CTA tile 64x128, 8 warps of 32x32. A fp32: register prefetch + cvt
// at STS (double buffer). B fp16: cp.async double buffer (R13-proven WAIT0
// pattern). One __syncthreads per chunk. Static smem 30.7 KB, 2 CTAs/SM.
// Launched twice (n0 = 0, 128) so agg of the first column half can overlap
// the second launch on another stream.
// ===========================================================================
__global__ __launch_bounds__(256, 2) void gemm_a_half_kernel(
    const float* __restrict__ A, const __half* __restrict__ B,
    const float* __restrict__ bias, __half* __restrict__ C, int M, int n0)
{
    __shared__ __half sA[2][64 * SROWH];
    __shared__ __half sB[2][128 * SROWH];

    const int tid  = threadIdx.x;
    const int warp = tid >> 5;
    const int lane = tid & 31;
    const int g    = lane >> 2;
    const int tg   = lane & 3;
    const int m0   = (int)blockIdx.x * 64;
    const int wm   = (warp >> 2) * 32;
    const int wn   = (warp & 3) * 32;

    // A staging: 64 rows x 32 floats; thread owns row tid>>2, 8 floats at (tid&3)*8
    const int arow = tid >> 2;
    const int acol = (tid & 3) * 8;
    const bool va  = (m0 + arow) < M;
    // B staging: 128 rows x 32 halves = 512 granules -> 2 per thread
    const int br0 = tid >> 2,         bg0 = (tid & 3) * 8;
    const int br1 = (tid + 256) >> 2, bg1 = ((tid + 256) & 3) * 8;

    float acc[2][4][4];
    #pragma unroll
    for (int i = 0; i < 2; i++)
        #pragma unroll
        for (int j = 0; j < 4; j++)
            #pragma unroll
            for (int r = 0; r < 4; r++) acc[i][j][r] = 0.f;

    // ---- prologue: stage chunk 0 ----
    cp_async16(&sB[0][br0 * SROWH + bg0], B + (size_t)(n0 + br0) * 256 + bg0, true);
    cp_async16(&sB[0][br1 * SROWH + bg1], B + (size_t)(n0 + br1) * 256 + bg1, true);
    CP_COMMIT();
    {
        float4 v0 = va ? *(const float4*)(A + (size_t)(m0 + arow) * 256 + acol)
                       : make_float4(0.f, 0.f, 0.f, 0.f);
        float4 v1 = va ? *(const float4*)(A + (size_t)(m0 + arow) * 256 + acol + 4)
                       : make_float4(0.f, 0.f, 0.f, 0.f);
        *(uint4*)&sA[0][arow * SROWH + acol] =
            make_uint4(pack_h2(v0.x, v0.y), pack_h2(v0.z, v0.w),
                       pack_h2(v1.x, v1.y), pack_h2(v1.z, v1.w));
    }
    CP_WAIT0();
    __syncthreads();

    const uint32_t uA0 = (uint32_t)__cvta_generic_to_shared(&sA[0][0]);
    const uint32_t uA1 = (uint32_t)__cvta_generic_to_shared(&sA[1][0]);
    const uint32_t uB0 = (uint32_t)__cvta_generic_to_shared(&sB[0][0]);
    const uint32_t uB1 = (uint32_t)__cvta_generic_to_shared(&sB[1][0]);
    const uint32_t offA = (uint32_t)(((lane & 15) * SROWH + (lane >> 4) * 8) * 2);
    const uint32_t offB = (uint32_t)((((lane >> 4) * 8 + (lane & 7)) * SROWH
                                      + ((lane >> 3) & 1) * 8) * 2);

    #pragma unroll 1
    for (int c = 0; c < 8; c++) {
        // issue B chunk c+1 async; reg-prefetch A chunk c+1
        float4 pa0, pa1;
        if (c < 7) {
            const int kk = (c + 1) * 32;
            __half* dB = ((c + 1) & 1) ? &sB[1][0] : &sB[0][0];
            cp_async16(&dB[br0 * SROWH + bg0], B + (size_t)(n0 + br0) * 256 + kk + bg0, true);
            cp_async16(&dB[br1 * SROWH + bg1], B + (size_t)(n0 + br1) * 256 + kk + bg1, true);
            CP_COMMIT();
            pa0 = va ? *(const float4*)(A + (size_t)(m0 + arow) * 256 + kk + acol)
                     : make_float4(0.f, 0.f, 0.f, 0.f);
            pa1 = va ? *(const float4*)(A + (size_t)(m0 + arow) * 256 + kk + acol + 4)
                     : make_float4(0.f, 0.f, 0.f, 0.f);
        }

        // compute chunk c
        const uint32_t ubA = (c & 1) ? uA1 : uA0;
        const uint32_t ubB = (c & 1) ? uB1 : uB0;
        #pragma unroll
        for (int ks = 0; ks < 2; ks++) {
            uint32_t af[2][4];
            #pragma unroll
            for (int mf = 0; mf < 2; mf++)
                ldmatrix_x4(af[mf], ubA + offA
                            + (uint32_t)(((wm + mf * 16) * SROWH + ks * 16) * 2));
            uint32_t bf[2][4];
            #pragma unroll
            for (int p = 0; p < 2; p++)
                ldmatrix_x4(bf[p], ubB + offB
                            + (uint32_t)(((wn + p * 16) * SROWH + ks * 16) * 2));
            #pragma unroll
            for (int mf = 0; mf < 2; mf++)
                #pragma unroll
                for (int nf = 0; nf < 4; nf++)
                    mma_f16_f32acc(acc[mf][nf], af[mf], bf[nf >> 1][(nf & 1) * 2],
                                   bf[nf >> 1][(nf & 1) * 2 + 1]);
        }

        // store prefetched A; await B; swap
        if (c < 7) {
            __half* dA = ((c + 1) & 1) ? &sA[1][0] : &sA[0][0];
            *(uint4*)&dA[arow * SROWH + acol] =
                make_uint4(pack_h2(pa0.x, pa0.y), pack_h2(pa0.z, pa0.w),
                           pack_h2(pa1.x, pa1.y), pack_h2(pa1.z, pa1.w));
            CP_WAIT0();
        }
        __syncthreads();
    }

    // ---- epilogue: bias + relu, fp16 store (row stride 256) ----
    #pragma unroll
    for (int mf = 0; mf < 2; mf++) {
        #pragma unroll
        for (int half = 0; half < 2; half++) {
            const int m = m0 + wm + mf * 16 + g + half * 8;
            if (m < M) {
                #pragma unroll
                for (int nf = 0; nf < 4; nf++) {
                    const int cc = n0 + wn + nf * 8 + tg * 2;
                    const float v0 = fmaxf(acc[mf][nf][half * 2 + 0] + __ldg(&bias[cc]),     0.f);
                    const float v1 = fmaxf(acc[mf][nf][half * 2 + 1] + __ldg(&bias[cc + 1]), 0.f);
                    *(uint32_t*)(C + (size_t)m * 256 + cc) = pack_h2(v0, v1);
                }
            }
        }
    }
}

// ===========================================================================
// agg half: h_agg[n, colOff..colOff+127] = weighted mean of QH gather over
// that column half (column-separable). One warp per node, 4 cols/lane
// (uint2 loads), unroll 10 for MLP. doSelf != 0 also copies h[nodeset[n]]
// (fp32->fp16, all 256 cols) into the first half of the concat row.
// ===========================================================================
__global__ __launch_bounds__(256) void agg_half_kernel(
    const float* __restrict__ h, const int* __restrict__ nodeset,
    const int* __restrict__ nb_nodes, const float* __restrict__ nb_w,
    int colOff, int doSelf)
{
    __shared__ int   s_idx[8][TN];
    __shared__ float s_w[8][TN];

    const int tid  = threadIdx.x;
    const int warp = tid >> 5;
    const int lane = tid & 31;
    const int n    = blockIdx.x * 8 + warp;   // 2500 blocks exact

    for (int j = lane; j < TN; j += 32) {
        s_idx[warp][j] = nb_nodes[n * TN + j];
        s_w[warp][j]   = nb_w[n * TN + j];
    }
    __syncwarp();

    float wsum = 0.f;
    #pragma unroll
    for (int t = 0; t < TN; t++) wsum += s_w[warp][t];

    const int colb = colOff + lane * 4;
    float acc[4] = {0.f, 0.f, 0.f, 0.f};

    #pragma unroll 10
    for (int t = 0; t < TN; t++) {
        const int   idx = s_idx[warp][t];
        const float w   = s_w[warp][t];
        union { uint2 u; __half2 h2[2]; } q;
        q.u = *(const uint2*)(g_qh + (size_t)idx * HIDF + colb);
        const float2 f0 = __half22float2(q.h2[0]);
        const float2 f1 = __half22float2(q.h2[1]);
        acc[0] += w * f0.x; acc[1] += w * f0.y;
        acc[2] += w * f1.x; acc[3] += w * f1.y;
    }
    const float inv = 1.f / wsum;
    union { uint2 u; __half2 h2[2]; } o;
    o.h2[0] = __float22half2_rn(make_float2(acc[0] * inv, acc[1] * inv));
    o.h2[1] = __float22half2_rn(make_float2(acc[2] * inv, acc[3] * inv));
    *(uint2*)(g_cat + (size_t)n * CATF + INF + colb) = o.u;

    if (doSelf) {
        const int self = nodeset[n];
        const int cb   = lane * 8;
        const float4 s0 = *(const float4*)(h + (size_t)self * INF + cb);
        const float4 s1 = *(const float4*)(h + (size_t)self * INF + cb + 4);
        union { uint4 u; __half2 h2[4]; } sc;
        sc.h2[0] = __float22half2_rn(make_float2(s0.x, s0.y));
        sc.h2[1] = __float22half2_rn(make_float2(s0.z, s0.w));
        sc.h2[2] = __float22half2_rn(make_float2(s1.x, s1.y));
        sc.h2[3] = __float22half2_rn(make_float2(s1.z, s1.w));
        *(uint4*)(g_cat + (size_t)n * CATF + cb) = sc.u;
    }
}

// ===========================================================================
// GEMM-C + fused L2 norm (R14-proven): out[m0..m0+63, :] =
//   normalize( relu( g_cat @ Ww^T + Wb ) ).  K=512, full N=256 per CTA.
// Both operands fp16, 3-stage cp.async ring, wait_group 1. 8 warps of 32x64.
// Epilogue: relu in regs -> per-row sumsq (quad shfl + smem atomics) ->
// rsqrt -> single fp32 store.
// ===========================================================================
#define GC_STAGEH ((64 + 256) * SROWH)
#define GC_SMEM   (3 * GC_STAGEH * 2 + 256)

__global__ __launch_bounds__(256, 2) void gemm_c_kernel(
    const __half* __restrict__ A, const __half* __restrict__ B,
    const float* __restrict__ bias, float* __restrict__ C, int M)
{
    extern __shared__ __half dsm[];
    float* s_ss = (float*)(dsm + 3 * GC_STAGEH);

    const int tid  = threadIdx.x;
    const int warp = tid >> 5;
    const int lane = tid & 31;
    const int g    = lane >> 2;
    const int tg   = lane & 3;
    const int m0   = (int)blockIdx.x * 64;
    const int wm   = (warp >> 2) * 32;
    const int wn   = (warp & 3) * 64;
    const int K    = 512;

    const int ar = tid >> 2, ag = (tid & 3) * 8;
    const bool va = (m0 + ar) < M;

    float acc[2][8][4];
    #pragma unroll
    for (int i = 0; i < 2; i++)
        #pragma unroll
        for (int j = 0; j < 8; j++)
            #pragma unroll
            for (int r = 0; r < 4; r++) acc[i][j][r] = 0.f;

    if (tid < 64) s_ss[tid] = 0.f;

    #pragma unroll
    for (int s = 0; s < 2; s++) {
        __half* dA = dsm + s * GC_STAGEH;
        __half* dB = dA + 64 * SROWH;
        cp_async16(&dA[ar * SROWH + ag], A + (size_t)(m0 + ar) * K + s * 32 + ag, va);
        #pragma unroll
        for (int t = 0; t < 4; t++) {
            const int i  = tid + t * 256;
            const int br = i >> 2, bg = (i & 3) * 8;
            cp_async16(&dB[br * SROWH + bg], B + (size_t)br * K + s * 32 + bg, true);
        }
        CP_COMMIT();
    }
    CP_WAIT1();
    __syncthreads();

    const uint32_t uRing = (uint32_t)__cvta_generic_to_shared(dsm);
    const uint32_t offA  = (uint32_t)(((lane & 15) * SROWH + (lane >> 4) * 8) * 2);
    const uint32_t offB  = (uint32_t)((((lane >> 4) * 8 + (lane & 7)) * SROWH
                                       + ((lane >> 3) & 1) * 8) * 2);

    #pragma unroll 1
    for (int c = 0; c < 16; c++) {
        if (c + 2 < 16) {
            const int kk = (c + 2) * 32;
            __half* dA = dsm + ((c + 2) % 3) * GC_STAGEH;
            __half* dB = dA + 64 * SROWH;
            cp_async16(&dA[ar * SROWH + ag], A + (size_t)(m0 + ar) * K + kk + ag, va);
            #pragma unroll
            for (int t = 0; t < 4; t++) {
                const int i  = tid + t * 256;
                const int br = i >> 2, bg = (i & 3) * 8;
                cp_async16(&dB[br * SROWH + bg], B + (size_t)br * K + kk + bg, true);
            }
            CP_COMMIT();
        }

        const uint32_t uS  = uRing + (uint32_t)((c % 3) * GC_STAGEH * 2);
        const uint32_t ubA = uS;
        const uint32_t ubB = uS + (uint32_t)(64 * SROWH * 2);
        #pragma unroll
        for (int ks = 0; ks < 2; ks++) {
            uint32_t af[2][4];
            #pragma unroll
            for (int mf = 0; mf < 2; mf++)
                ldmatrix_x4(af[mf], ubA + offA
                            + (uint32_t)(((wm + mf * 16) * SROWH + ks * 16) * 2));
            uint32_t bf[4][4];
            #pragma unroll
            for (int p = 0; p < 4; p++)
                ldmatrix_x4(bf[p], ubB + offB
                            + (uint32_t)(((wn + p * 16) * SROWH + ks * 16) * 2));
            #pragma unroll
            for (int mf = 0; mf < 2; mf++)
                #pragma unroll
                for (int nf = 0; nf < 8; nf++)
                    mma_f16_f32acc(acc[mf][nf], af[mf], bf[nf >> 1][(nf & 1) * 2],
                                   bf[nf >> 1][(nf & 1) * 2 + 1]);
        }

        if (c + 1 < 16) CP_WAIT1();
        __syncthreads();
    }

    // ---- epilogue: relu, fused per-row L2 norm, fp32 store ----
    float ss[2][2];
    #pragma unroll
    for (int mf = 0; mf < 2; mf++)
        #pragma unroll
        for (int half = 0; half < 2; half++) {
            float s = 0.f;
            #pragma unroll
            for (int nf = 0; nf < 8; nf++) {
                const int cc = wn + nf * 8 + tg * 2;
                float v0 = fmaxf(acc[mf][nf][half * 2 + 0] + __ldg(&bias[cc]),     0.f);
                float v1 = fmaxf(acc[mf][nf][half * 2 + 1] + __ldg(&bias[cc + 1]), 0.f);
                acc[mf][nf][half * 2 + 0] = v0;
                acc[mf][nf][half * 2 + 1] = v1;
                s += v0 * v0 + v1 * v1;
            }
            ss[mf][half] = s;
        }
    #pragma unroll
    for (int mf = 0; mf < 2; mf++)
        #pragma unroll
        for (int half = 0; half < 2; half++) {
            ss[mf][half] += __shfl_xor_sync(0xffffffffu, ss[mf][half], 1);
            ss[mf][half] += __shfl_xor_sync(0xffffffffu, ss[mf][half], 2);
        }
    if (tg == 0) {
        #pragma unroll
        for (int mf = 0; mf < 2; mf++)
            #pragma unroll
            for (int half = 0; half < 2; half++)
                atomicAdd(&s_ss[wm + mf * 16 + g + half * 8], ss[mf][half]);
    }
    __syncthreads();

    #pragma unroll
    for (int mf = 0; mf < 2; mf++)
        #pragma unroll
        for (int half = 0; half < 2; half++) {
            const int r = wm + mf * 16 + g + half * 8;
            const int m = m0 + r;
            if (m < M) {
                const float inv = rsqrtf(s_ss[r]);
                #pragma unroll
                for (int nf = 0; nf < 8; nf++) {
                    const int cc = wn + nf * 8 + tg * 2;
                    *(float2*)(C + (size_t)m * 256 + cc) =
                        make_float2(acc[mf][nf][half * 2 + 0] * inv,
                                    acc[mf][nf][half * 2 + 1] * inv);
                }
            }
        }
}

// ---------------------------------------------------------------------------
extern "C" void kernel_launch(void* const* d_in, const int* in_sizes, int n_in,
                              void* d_out, int out_size)
{
    const float* h        = (const float*)d_in[0];
    const int*   nodeset  = (const int*)d_in[1];
    const int*   nb_nodes = (const int*)d_in[2];
    const float* nb_w     = (const float*)d_in[3];
    const float* Qw       = (const float*)d_in[4];
    const float* Qb       = (const float*)d_in[5];
    const float* Ww       = (const float*)d_in[6];
    const float* Wb       = (const float*)d_in[7];
    float*       out      = (float*)d_out;

    __half* qh   = nullptr;
    __half* cat  = nullptr;
    __half* qw16 = nullptr;
    __half* ww16 = nullptr;
    cudaGetSymbolAddress((void**)&qh,   g_qh);
    cudaGetSymbolAddress((void**)&cat,  g_cat);
    cudaGetSymbolAddress((void**)&qw16, g_qw16);
    cudaGetSymbolAddress((void**)&ww16, g_ww16);

    // one-time infra (streams/events/attrs created outside capture on the
    // first, non-captured correctness call; reused on every call after)
    static cudaStream_t s1  = nullptr;
    static cudaEvent_t  eA0 = nullptr, eG0 = nullptr;
    if (!s1) {
        cudaStreamCreateWithFlags(&s1, cudaStreamNonBlocking);
        cudaEventCreateWithFlags(&eA0, cudaEventDisableTiming);
        cudaEventCreateWithFlags(&eG0, cudaEventDisableTiming);
        cudaFuncSetAttribute(gemm_c_kernel,
                             cudaFuncAttributeMaxDynamicSharedMemorySize, GC_SMEM);
    }

    const int tilesA = (NODES_TOTAL + 63) / 64;   // 1563
    const int aggBlk = NNODES / 8;                // 2500

    // k0 (main): weights -> fp16
    cvt_weights_kernel<<<192, 256>>>(Qw, Ww);

    // k1 (main): QH cols 0..127
    gemm_a_half_kernel<<<tilesA, 256>>>(h, qw16, Qb, qh, NODES_TOTAL, 0);
    cudaEventRecord(eA0, 0);

    // k2 (main): QH cols 128..255
    gemm_a_half_kernel<<<tilesA, 256>>>(h, qw16, Qb, qh, NODES_TOTAL, 128);

    // k3 (side, overlaps k2): agg of QH cols 0..127 + self copy
    cudaStreamWaitEvent(s1, eA0, 0);
    agg_half_kernel<<<aggBlk, 256, 0, s1>>>(h, nodeset, nb_nodes, nb_w, 0, 1);
    cudaEventRecord(eG0, s1);

    // k4 (main, after k2): agg of QH cols 128..255
    agg_half_kernel<<<aggBlk, 256>>>(h, nodeset, nb_nodes, nb_w, 128, 0);

    // join side stream, then k5 (main): fused GEMM-C + L2 norm
    cudaStreamWaitEvent(0, eG0, 0);
    {
        const int tilesM = (NNODES + 63) / 64;    // 313
        gemm_c_kernel<<<tilesM, 256, GC_SMEM>>>(cat, ww16, Wb, out, NNODES);
    }
}

// round 16
// speedup vs baseline: 1.2622x; 1.2622x over previous
#include <cuda_runtime.h>
#include <cuda_fp16.h>
#include <cstdint>

#define NODES_TOTAL 100000
#define NNODES      20000
#define TN          50
#define INF         256
#define HIDF        256
#define OUTF        256
#define CATF        512

// Scratch (static __device__ arrays: allocation-free per harness rules)
__device__ __align__(16) __half g_qh[(size_t)NODES_TOTAL * HIDF];  // 51.2 MB
__device__ __align__(16) __half g_cat[(size_t)NNODES * CATF];      // 20.5 MB
__device__ __align__(16) __half g_qw16[INF * HIDF];                // Qw fp16
__device__ __align__(16) __half g_ww16[OUTF * CATF];               // Ww fp16

// ---------------------------------------------------------------------------
// helpers
// ---------------------------------------------------------------------------
__device__ __forceinline__ void mma_f16_f32acc(float c[4], const uint32_t a[4],
                                               uint32_t b0, uint32_t b1) {
    asm volatile("mma.sync.aligned.m16n8k16.row.col.f32.f16.f16.f32 "
                 "{%0,%1,%2,%3}, {%4,%5,%6,%7}, {%8,%9}, {%0,%1,%2,%3};"
                 : "+f"(c[0]), "+f"(c[1]), "+f"(c[2]), "+f"(c[3])
                 : "r"(a[0]), "r"(a[1]), "r"(a[2]), "r"(a[3]), "r"(b0), "r"(b1));
}

__device__ __forceinline__ void ldmatrix_x4(uint32_t r[4], uint32_t saddr) {
    asm volatile("ldmatrix.sync.aligned.m8n8.x4.shared.b16 {%0,%1,%2,%3}, [%4];"
                 : "=r"(r[0]), "=r"(r[1]), "=r"(r[2]), "=r"(r[3]) : "r"(saddr));
}

__device__ __forceinline__ uint32_t pack_h2(float x, float y) {
    __half2 h = __float22half2_rn(make_float2(x, y));
    return *(uint32_t*)&h;
}

__device__ __forceinline__ void cp_async16(void* smem_dst, const void* gmem_src, bool pred) {
    uint32_t saddr = (uint32_t)__cvta_generic_to_shared(smem_dst);
    int sz = pred ? 16 : 0;
    asm volatile("cp.async.cg.shared.global [%0], [%1], 16, %2;"
                 :: "r"(saddr), "l"(gmem_src), "r"(sz));
}
#define CP_COMMIT() asm volatile("cp.async.commit_group;")
#define CP_WAIT0()  asm volatile("cp.async.wait_group 0;")
#define CP_WAIT1()  asm volatile("cp.async.wait_group 1;")

#define SROWH 40   // smem row stride in halves (80B -> conflict-free ldmatrix)

// ---------------------------------------------------------------------------
// k0: one-shot weight conversion fp32 -> fp16 (RN)
// ---------------------------------------------------------------------------
__global__ __launch_bounds__(256) void cvt_weights_kernel(
    const float* __restrict__ Qw, const float* __restrict__ Ww)
{
    const int i = blockIdx.x * 256 + threadIdx.x;
    if (i < 16384) {
        const float4 v = ((const float4*)Qw)[i];
        ((uint2*)g_qw16)[i] = make_uint2(pack_h2(v.x, v.y), pack_h2(v.z, v.w));
    } else if (i < 49152) {
        const int j = i - 16384;
        const float4 v = ((const float4*)Ww)[j];
        ((uint2*)g_ww16)[j] = make_uint2(pack_h2(v.x, v.y), pack_h2(v.z, v.w));
    }
}

// ===========================================================================
// GEMM-A (R13-proven): QH[m0..m0+63, 0..255] = relu( h @ Qw^T + Qb ), fp16.
// CTA tile 64x256 (full N -> A read once). 8 warps of 32x64. A fp32: register
// prefetch + cvt at STS (double buffer). B fp16: cp.async double buffer,
// WAIT0 after compute. One __syncthreads per chunk. 51.2 KB dyn smem.
// ===========================================================================
#define GA_SMEM ((2 * 64 * SROWH + 2 * 256 * SROWH) * 2)   // 51200 B

__global__ __launch_bounds__(256, 2) void gemm_a_kernel(
    const float* __restrict__ A, const __half* __restrict__ B,
    const float* __restrict__ bias, __half* __restrict__ C, int M)
{
    extern __shared__ __half dsm[];
    __half* sA0 = dsm;
    __half* sA1 = dsm + 64 * SROWH;
    __half* sB0 = dsm + 2 * 64 * SROWH;
    __half* sB1 = sB0 + 256 * SROWH;

    const int tid  = threadIdx.x;
    const int warp = tid >> 5;
    const int lane = tid & 31;
    const int g    = lane >> 2;
    const int tg   = lane & 3;
    const int m0   = (int)blockIdx.x * 64;
    const int wm   = (warp >> 2) * 32;
    const int wn   = (warp & 3) * 64;

    const int arow = tid >> 2;
    const int acol = (tid & 3) * 8;
    const bool va  = (m0 + arow) < M;

    float acc[2][8][4];
    #pragma unroll
    for (int i = 0; i < 2; i++)
        #pragma unroll
        for (int j = 0; j < 8; j++)
            #pragma unroll
            for (int r = 0; r < 4; r++) acc[i][j][r] = 0.f;

    // ---- prologue: stage chunk 0 ----
    #pragma unroll
    for (int t = 0; t < 4; t++) {
        const int i  = tid + t * 256;
        const int br = i >> 2, bg = (i & 3) * 8;
        cp_async16(&sB0[br * SROWH + bg], B + (size_t)br * 256 + bg, true);
    }
    CP_COMMIT();
    {
        float4 v0 = va ? *(const float4*)(A + (size_t)(m0 + arow) * 256 + acol)
                       : make_float4(0.f, 0.f, 0.f, 0.f);
        float4 v1 = va ? *(const float4*)(A + (size_t)(m0 + arow) * 256 + acol + 4)
                       : make_float4(0.f, 0.f, 0.f, 0.f);
        *(uint4*)&sA0[arow * SROWH + acol] =
            make_uint4(pack_h2(v0.x, v0.y), pack_h2(v0.z, v0.w),
                       pack_h2(v1.x, v1.y), pack_h2(v1.z, v1.w));
    }
    CP_WAIT0();
    __syncthreads();

    const uint32_t uA0  = (uint32_t)__cvta_generic_to_shared(sA0);
    const uint32_t uA1  = (uint32_t)__cvta_generic_to_shared(sA1);
    const uint32_t uB0  = (uint32_t)__cvta_generic_to_shared(sB0);
    const uint32_t uB1  = (uint32_t)__cvta_generic_to_shared(sB1);
    const uint32_t offA = (uint32_t)(((lane & 15) * SROWH + (lane >> 4) * 8) * 2);
    const uint32_t offB = (uint32_t)((((lane >> 4) * 8 + (lane & 7)) * SROWH
                                      + ((lane >> 3) & 1) * 8) * 2);

    #pragma unroll 1
    for (int c = 0; c < 8; c++) {
        // issue B chunk c+1 async; reg-prefetch A chunk c+1
        float4 pa0, pa1;
        if (c < 7) {
            const int kk = (c + 1) * 32;
            __half* dB = ((c + 1) & 1) ? sB1 : sB0;
            #pragma unroll
            for (int t = 0; t < 4; t++) {
                const int i  = tid + t * 256;
                const int br = i >> 2, bg = (i & 3) * 8;
                cp_async16(&dB[br * SROWH + bg], B + (size_t)br * 256 + kk + bg, true);
            }
            CP_COMMIT();
            pa0 = va ? *(const float4*)(A + (size_t)(m0 + arow) * 256 + kk + acol)
                     : make_float4(0.f, 0.f, 0.f, 0.f);
            pa1 = va ? *(const float4*)(A + (size_t)(m0 + arow) * 256 + kk + acol + 4)
                     : make_float4(0.f, 0.f, 0.f, 0.f);
        }

        // compute chunk c
        const uint32_t ubA = (c & 1) ? uA1 : uA0;
        const uint32_t ubB = (c & 1) ? uB1 : uB0;
        #pragma unroll
        for (int ks = 0; ks < 2; ks++) {
            uint32_t af[2][4];
            #pragma unroll
            for (int mf = 0; mf < 2; mf++)
                ldmatrix_x4(af[mf], ubA + offA
                            + (uint32_t)(((wm + mf * 16) * SROWH + ks * 16) * 2));
            uint32_t bf[4][4];
            #pragma unroll
            for (int p = 0; p < 4; p++)
                ldmatrix_x4(bf[p], ubB + offB
                            + (uint32_t)(((wn + p * 16) * SROWH + ks * 16) * 2));
            #pragma unroll
            for (int mf = 0; mf < 2; mf++)
                #pragma unroll
                for (int nf = 0; nf < 8; nf++)
                    mma_f16_f32acc(acc[mf][nf], af[mf], bf[nf >> 1][(nf & 1) * 2],
                                   bf[nf >> 1][(nf & 1) * 2 + 1]);
        }

        // store prefetched A; await B; swap
        if (c < 7) {
            __half* dA = ((c + 1) & 1) ? sA1 : sA0;
            *(uint4*)&dA[arow * SROWH + acol] =
                make_uint4(pack_h2(pa0.x, pa0.y), pack_h2(pa0.z, pa0.w),
                           pack_h2(pa1.x, pa1.y), pack_h2(pa1.z, pa1.w));
            CP_WAIT0();
        }
        __syncthreads();
    }

    // ---- epilogue: bias + relu, fp16 store (row stride 256) ----
    #pragma unroll
    for (int mf = 0; mf < 2; mf++) {
        #pragma unroll
        for (int half = 0; half < 2; half++) {
            const int m = m0 + wm + mf * 16 + g + half * 8;
            if (m < M) {
                #pragma unroll
                for (int nf = 0; nf < 8; nf++) {
                    const int cc = wn + nf * 8 + tg * 2;
                    const float v0 = fmaxf(acc[mf][nf][half * 2 + 0] + __ldg(&bias[cc]),     0.f);
                    const float v1 = fmaxf(acc[mf][nf][half * 2 + 1] + __ldg(&bias[cc + 1]), 0.f);
                    *(uint32_t*)(C + (size_t)m * 256 + cc) = pack_h2(v0, v1);
                }
            }
        }
    }
}

// ===========================================================================
// GEMM-C + fused L2 norm: out[m0..m0+63, :] =
//   normalize( relu( g_cat @ Ww^T + Wb ) ). K=512, full N=256 per CTA.
// 2-stage WAIT0 double buffer (NOT the 3-stage ring: that hit the 128-reg
// cap in R14 and regressed). 8 warps of 32x64. Epilogue: relu in regs ->
// per-row sumsq (quad shfl + smem atomics) -> rsqrt -> single fp32 store.
// 313 CTAs, 51.5 KB dyn smem, 2 CTAs/SM.
// ===========================================================================
#define GC_SMEM ((2 * 64 * SROWH + 2 * 256 * SROWH) * 2 + 256)

__global__ __launch_bounds__(256, 2) void gemm_c_kernel(
    const __half* __restrict__ A, const __half* __restrict__ B,
    const float* __restrict__ bias, float* __restrict__ C, int M)
{
    extern __shared__ __half dsm[];
    __half* sA0 = dsm;
    __half* sA1 = dsm + 64 * SROWH;
    __half* sB0 = dsm + 2 * 64 * SROWH;
    __half* sB1 = sB0 + 256 * SROWH;
    float*  s_ss = (float*)(sB1 + 256 * SROWH);   // [64] per-row sumsq

    const int tid  = threadIdx.x;
    const int warp = tid >> 5;
    const int lane = tid & 31;
    const int g    = lane >> 2;
    const int tg   = lane & 3;
    const int m0   = (int)blockIdx.x * 64;
    const int wm   = (warp >> 2) * 32;
    const int wn   = (warp & 3) * 64;
    const int K    = 512;

    const int ar = tid >> 2, ag = (tid & 3) * 8;
    const bool va = (m0 + ar) < M;

    float acc[2][8][4];
    #pragma unroll
    for (int i = 0; i < 2; i++)
        #pragma unroll
        for (int j = 0; j < 8; j++)
            #pragma unroll
            for (int r = 0; r < 4; r++) acc[i][j][r] = 0.f;

    if (tid < 64) s_ss[tid] = 0.f;

    // ---- prologue: async-stage chunk 0 ----
    cp_async16(&sA0[ar * SROWH + ag], A + (size_t)(m0 + ar) * K + ag, va);
    #pragma unroll
    for (int t = 0; t < 4; t++) {
        const int i  = tid + t * 256;
        const int br = i >> 2, bg = (i & 3) * 8;
        cp_async16(&sB0[br * SROWH + bg], B + (size_t)br * K + bg, true);
    }
    CP_COMMIT();
    CP_WAIT0();
    __syncthreads();

    const uint32_t uA0  = (uint32_t)__cvta_generic_to_shared(sA0);
    const uint32_t uA1  = (uint32_t)__cvta_generic_to_shared(sA1);
    const uint32_t uB0  = (uint32_t)__cvta_generic_to_shared(sB0);
    const uint32_t uB1  = (uint32_t)__cvta_generic_to_shared(sB1);
    const uint32_t offA = (uint32_t)(((lane & 15) * SROWH + (lane >> 4) * 8) * 2);
    const uint32_t offB = (uint32_t)((((lane >> 4) * 8 + (lane & 7)) * SROWH
                                      + ((lane >> 3) & 1) * 8) * 2);

    #pragma unroll 1
    for (int c = 0; c < 16; c++) {
        if (c < 15) {
            const int kk = (c + 1) * 32;
            __half* dA = ((c + 1) & 1) ? sA1 : sA0;
            __half* dB = ((c + 1) & 1) ? sB1 : sB0;
            cp_async16(&dA[ar * SROWH + ag], A + (size_t)(m0 + ar) * K + kk + ag, va);
            #pragma unroll
            for (int t = 0; t < 4; t++) {
                const int i  = tid + t * 256;
                const int br = i >> 2, bg = (i & 3) * 8;
                cp_async16(&dB[br * SROWH + bg], B + (size_t)br * K + kk + bg, true);
            }
            CP_COMMIT();
        }

        const uint32_t ubA = (c & 1) ? uA1 : uA0;
        const uint32_t ubB = (c & 1) ? uB1 : uB0;
        #pragma unroll
        for (int ks = 0; ks < 2; ks++) {
            uint32_t af[2][4];
            #pragma unroll
            for (int mf = 0; mf < 2; mf++)
                ldmatrix_x4(af[mf], ubA + offA
                            + (uint32_t)(((wm + mf * 16) * SROWH + ks * 16) * 2));
            uint32_t bf[4][4];
            #pragma unroll
            for (int p = 0; p < 4; p++)
                ldmatrix_x4(bf[p], ubB + offB
                            + (uint32_t)(((wn + p * 16) * SROWH + ks * 16) * 2));
            #pragma unroll
            for (int mf = 0; mf < 2; mf++)
                #pragma unroll
                for (int nf = 0; nf < 8; nf++)
                    mma_f16_f32acc(acc[mf][nf], af[mf], bf[nf >> 1][(nf & 1) * 2],
                                   bf[nf >> 1][(nf & 1) * 2 + 1]);
        }

        if (c < 15) CP_WAIT0();
        __syncthreads();
    }

    // ---- epilogue: relu in regs, fused per-row L2 norm, fp32 store ----
    float ss[2][2];
    #pragma unroll
    for (int mf = 0; mf < 2; mf++)
        #pragma unroll
        for (int half = 0; half < 2; half++) {
            float s = 0.f;
            #pragma unroll
            for (int nf = 0; nf < 8; nf++) {
                const int cc = wn + nf * 8 + tg * 2;
                float v0 = fmaxf(acc[mf][nf][half * 2 + 0] + __ldg(&bias[cc]),     0.f);
                float v1 = fmaxf(acc[mf][nf][half * 2 + 1] + __ldg(&bias[cc + 1]), 0.f);
                acc[mf][nf][half * 2 + 0] = v0;
                acc[mf][nf][half * 2 + 1] = v1;
                s += v0 * v0 + v1 * v1;
            }
            ss[mf][half] = s;
        }
    #pragma unroll
    for (int mf = 0; mf < 2; mf++)
        #pragma unroll
        for (int half = 0; half < 2; half++) {
            ss[mf][half] += __shfl_xor_sync(0xffffffffu, ss[mf][half], 1);
            ss[mf][half] += __shfl_xor_sync(0xffffffffu, ss[mf][half], 2);
        }
    if (tg == 0) {
        #pragma unroll
        for (int mf = 0; mf < 2; mf++)
            #pragma unroll
            for (int half = 0; half < 2; half++)
                atomicAdd(&s_ss[wm + mf * 16 + g + half * 8], ss[mf][half]);
    }
    __syncthreads();

    #pragma unroll
    for (int mf = 0; mf < 2; mf++)
        #pragma unroll
        for (int half = 0; half < 2; half++) {
            const int r = wm + mf * 16 + g + half * 8;
            const int m = m0 + r;
            if (m < M) {
                const float inv = rsqrtf(s_ss[r]);
                #pragma unroll
                for (int nf = 0; nf < 8; nf++) {
                    const int cc = wn + nf * 8 + tg * 2;
                    *(float2*)(C + (size_t)m * 256 + cc) =
                        make_float2(acc[mf][nf][half * 2 + 0] * inv,
                                    acc[mf][nf][half * 2 + 1] * inv);
                }
            }
        }
}

// ---------------------------------------------------------------------------
// Aggregation (R13-proven): h_agg[n] = sum_t w*QH[nb[n,t]] / sum_t w.
// QH fp16 (L2-resident). One warp per node; also copies h[nodeset[n]]
// (fp32->fp16) into the first half of the concat row.
// ---------------------------------------------------------------------------
__global__ __launch_bounds__(256) void agg_kernel(
    const float* __restrict__ h, const int* __restrict__ nodeset,
    const int* __restrict__ nb_nodes, const float* __restrict__ nb_w)
{
    __shared__ int   s_idx[8][TN];
    __shared__ float s_w[8][TN];

    const int tid  = threadIdx.x;
    const int warp = tid >> 5;
    const int lane = tid & 31;
    const int n    = blockIdx.x * 8 + warp;   // 2500 blocks exact

    for (int j = lane; j < TN; j += 32) {
        s_idx[warp][j] = nb_nodes[n * TN + j];
        s_w[warp][j]   = nb_w[n * TN + j];
    }
    __syncwarp();

    float wsum = 0.f;
    #pragma unroll
    for (int t = 0; t < TN; t++) wsum += s_w[warp][t];

    const int colb = lane * 8;
    float acc[8];
    #pragma unroll
    for (int i = 0; i < 8; i++) acc[i] = 0.f;

    #pragma unroll 10
    for (int t = 0; t < TN; t++) {
        const int   idx = s_idx[warp][t];
        const float w   = s_w[warp][t];
        union { uint4 u; __half2 h2[4]; } q;
        q.u = *(const uint4*)(g_qh + (size_t)idx * HIDF + colb);
        #pragma unroll
        for (int i = 0; i < 4; i++) {
            const float2 f = __half22float2(q.h2[i]);
            acc[2 * i]     += w * f.x;
            acc[2 * i + 1] += w * f.y;
        }
    }
    const float inv = 1.f / wsum;
    union { uint4 u; __half2 h2[4]; } o;
    #pragma unroll
    for (int i = 0; i < 4; i++)
        o.h2[i] = __float22half2_rn(make_float2(acc[2 * i] * inv, acc[2 * i + 1] * inv));
    *(uint4*)(g_cat + (size_t)n * CATF + INF + colb) = o.u;

    const int self = nodeset[n];
    const float4 s0 = *(const float4*)(h + (size_t)self * INF + colb);
    const float4 s1 = *(const float4*)(h + (size_t)self * INF + colb + 4);
    union { uint4 u; __half2 h2[4]; } sc;
    sc.h2[0] = __float22half2_rn(make_float2(s0.x, s0.y));
    sc.h2[1] = __float22half2_rn(make_float2(s0.z, s0.w));
    sc.h2[2] = __float22half2_rn(make_float2(s1.x, s1.y));
    sc.h2[3] = __float22half2_rn(make_float2(s1.z, s1.w));
    *(uint4*)(g_cat + (size_t)n * CATF + colb) = sc.u;
}

// ---------------------------------------------------------------------------
extern "C" void kernel_launch(void* const* d_in, const int* in_sizes, int n_in,
                              void* d_out, int out_size)
{
    const float* h        = (const float*)d_in[0];
    const int*   nodeset  = (const int*)d_in[1];
    const int*   nb_nodes = (const int*)d_in[2];
    const float* nb_w     = (const float*)d_in[3];
    const float* Qw       = (const float*)d_in[4];
    const float* Qb       = (const float*)d_in[5];
    const float* Ww       = (const float*)d_in[6];
    const float* Wb       = (const float*)d_in[7];
    float*       out      = (float*)d_out;

    __half* qh   = nullptr;
    __half* cat  = nullptr;
    __half* qw16 = nullptr;
    __half* ww16 = nullptr;
    cudaGetSymbolAddress((void**)&qh,   g_qh);
    cudaGetSymbolAddress((void**)&cat,  g_cat);
    cudaGetSymbolAddress((void**)&qw16, g_qw16);
    cudaGetSymbolAddress((void**)&ww16, g_ww16);

    static bool attr_done = false;
    if (!attr_done) {
        cudaFuncSetAttribute(gemm_a_kernel,
                             cudaFuncAttributeMaxDynamicSharedMemorySize, GA_SMEM);
        cudaFuncSetAttribute(gemm_c_kernel,
                             cudaFuncAttributeMaxDynamicSharedMemorySize, GC_SMEM);
        attr_done = true;
    }

    // k0: weights -> fp16 (once per launch; ~2us)
    cvt_weights_kernel<<<192, 256>>>(Qw, Ww);

    // k1: QH = relu(h @ Qw^T + Qb) -> fp16 [100000, 256]
    {
        const int tilesM = (NODES_TOTAL + 63) / 64;   // 1563
        gemm_a_kernel<<<tilesM, 256, GA_SMEM>>>(h, qw16, Qb, qh, NODES_TOTAL);
    }
    // k2: aggregate + self gather -> g_cat fp16 [20000, 512]
    agg_kernel<<<NNODES / 8, 256>>>(h, nodeset, nb_nodes, nb_w);

    // k3: out = normalize(relu(g_cat @ Ww^T + Wb))  [20000, 256] (norm fused)
    {
        const int tilesM = (NNODES + 63) / 64;        // 313
        gemm_c_kernel<<<tilesM, 256, GC_SMEM>>>(cat, ww16, Wb, out, NNODES);
    }
}

// round 17
// speedup vs baseline: 1.2786x; 1.0130x over previous
#include <cuda_runtime.h>
#include <cuda_fp16.h>
#include <cstdint>

#define NODES_TOTAL 100000
#define NNODES      20000
#define TN          50
#define INF         256
#define HIDF        256
#define OUTF        256
#define CATF        512

// Scratch (static __device__ arrays: allocation-free per harness rules)
__device__ __align__(16) __half g_qh[(size_t)NODES_TOTAL * HIDF];  // 51.2 MB
__device__ __align__(16) __half g_cat[(size_t)NNODES * CATF];      // 20.5 MB
__device__ __align__(16) __half g_qw16[INF * HIDF];                // Qw fp16
__device__ __align__(16) __half g_ww16[OUTF * CATF];               // Ww fp16

// ---------------------------------------------------------------------------
// helpers
// ---------------------------------------------------------------------------
__device__ __forceinline__ void mma_f16_f32acc(float c[4], const uint32_t a[4],
                                               uint32_t b0, uint32_t b1) {
    asm volatile("mma.sync.aligned.m16n8k16.row.col.f32.f16.f16.f32 "
                 "{%0,%1,%2,%3}, {%4,%5,%6,%7}, {%8,%9}, {%0,%1,%2,%3};"
                 : "+f"(c[0]), "+f"(c[1]), "+f"(c[2]), "+f"(c[3])
                 : "r"(a[0]), "r"(a[1]), "r"(a[2]), "r"(a[3]), "r"(b0), "r"(b1));
}

__device__ __forceinline__ void ldmatrix_x4(uint32_t r[4], uint32_t saddr) {
    asm volatile("ldmatrix.sync.aligned.m8n8.x4.shared.b16 {%0,%1,%2,%3}, [%4];"
                 : "=r"(r[0]), "=r"(r[1]), "=r"(r[2]), "=r"(r[3]) : "r"(saddr));
}

__device__ __forceinline__ uint32_t pack_h2(float x, float y) {
    __half2 h = __float22half2_rn(make_float2(x, y));
    return *(uint32_t*)&h;
}

__device__ __forceinline__ void cp_async16(void* smem_dst, const void* gmem_src, bool pred) {
    uint32_t saddr = (uint32_t)__cvta_generic_to_shared(smem_dst);
    int sz = pred ? 16 : 0;
    asm volatile("cp.async.cg.shared.global [%0], [%1], 16, %2;"
                 :: "r"(saddr), "l"(gmem_src), "r"(sz));
}
#define CP_COMMIT() asm volatile("cp.async.commit_group;")
#define CP_WAIT0()  asm volatile("cp.async.wait_group 0;")

#define SROWH 40   // smem row stride in halves (80B -> conflict-free ldmatrix)

// ---------------------------------------------------------------------------
// k0: Qw fp32 -> fp16 only (Ww conversion is folded into the agg kernel).
// 16384 float4 over 64 blocks x 256 threads.
// ---------------------------------------------------------------------------
__global__ __launch_bounds__(256) void cvt_qw_kernel(const float* __restrict__ Qw)
{
    const int i = blockIdx.x * 256 + threadIdx.x;
    const float4 v = ((const float4*)Qw)[i];
    ((uint2*)g_qw16)[i] = make_uint2(pack_h2(v.x, v.y), pack_h2(v.z, v.w));
}

// ===========================================================================
// GEMM-A (R13-proven loop): QH[m0..m0+63, 0..255] = relu(h @ Qw^T + Qb), fp16.
// CTA tile 64x256 (full N -> A read once). 8 warps of 32x64. A fp32: register
// prefetch + cvt at STS (double buffer). B fp16: cp.async double buffer,
// WAIT0 after compute. Bias pre-loaded into the accumulators (epilogue is
// relu+store only). One __syncthreads per chunk. 51.2 KB dyn smem.
// ===========================================================================
#define GA_SMEM ((2 * 64 * SROWH + 2 * 256 * SROWH) * 2)   // 51200 B

__global__ __launch_bounds__(256, 2) void gemm_a_kernel(
    const float* __restrict__ A, const __half* __restrict__ B,
    const float* __restrict__ bias, __half* __restrict__ C, int M)
{
    extern __shared__ __half dsm[];
    __half* sA0 = dsm;
    __half* sA1 = dsm + 64 * SROWH;
    __half* sB0 = dsm + 2 * 64 * SROWH;
    __half* sB1 = sB0 + 256 * SROWH;

    const int tid  = threadIdx.x;
    const int warp = tid >> 5;
    const int lane = tid & 31;
    const int g    = lane >> 2;
    const int tg   = lane & 3;
    const int m0   = (int)blockIdx.x * 64;
    const int wm   = (warp >> 2) * 32;
    const int wn   = (warp & 3) * 64;

    const int arow = tid >> 2;
    const int acol = (tid & 3) * 8;
    const bool va  = (m0 + arow) < M;

    // accumulators initialized with bias (C = bias + sum; relu at store)
    float acc[2][8][4];
    #pragma unroll
    for (int nf = 0; nf < 8; nf++) {
        const int cc = wn + nf * 8 + tg * 2;
        const float b0 = __ldg(&bias[cc]);
        const float b1 = __ldg(&bias[cc + 1]);
        #pragma unroll
        for (int mf = 0; mf < 2; mf++) {
            acc[mf][nf][0] = b0; acc[mf][nf][1] = b1;
            acc[mf][nf][2] = b0; acc[mf][nf][3] = b1;
        }
    }

    // ---- prologue: stage chunk 0 ----
    #pragma unroll
    for (int t = 0; t < 4; t++) {
        const int i  = tid + t * 256;
        const int br = i >> 2, bg = (i & 3) * 8;
        cp_async16(&sB0[br * SROWH + bg], B + (size_t)br * 256 + bg, true);
    }
    CP_COMMIT();
    {
        float4 v0 = va ? *(const float4*)(A + (size_t)(m0 + arow) * 256 + acol)
                       : make_float4(0.f, 0.f, 0.f, 0.f);
        float4 v1 = va ? *(const float4*)(A + (size_t)(m0 + arow) * 256 + acol + 4)
                       : make_float4(0.f, 0.f, 0.f, 0.f);
        *(uint4*)&sA0[arow * SROWH + acol] =
            make_uint4(pack_h2(v0.x, v0.y), pack_h2(v0.z, v0.w),
                       pack_h2(v1.x, v1.y), pack_h2(v1.z, v1.w));
    }
    CP_WAIT0();
    __syncthreads();

    const uint32_t uA0  = (uint32_t)__cvta_generic_to_shared(sA0);
    const uint32_t uA1  = (uint32_t)__cvta_generic_to_shared(sA1);
    const uint32_t uB0  = (uint32_t)__cvta_generic_to_shared(sB0);
    const uint32_t uB1  = (uint32_t)__cvta_generic_to_shared(sB1);
    const uint32_t offA = (uint32_t)(((lane & 15) * SROWH + (lane >> 4) * 8) * 2);
    const uint32_t offB = (uint32_t)((((lane >> 4) * 8 + (lane & 7)) * SROWH
                                      + ((lane >> 3) & 1) * 8) * 2);

    #pragma unroll 1
    for (int c = 0; c < 8; c++) {
        // issue B chunk c+1 async; reg-prefetch A chunk c+1
        float4 pa0, pa1;
        if (c < 7) {
            const int kk = (c + 1) * 32;
            __half* dB = ((c + 1) & 1) ? sB1 : sB0;
            #pragma unroll
            for (int t = 0; t < 4; t++) {
                const int i  = tid + t * 256;
                const int br = i >> 2, bg = (i & 3) * 8;
                cp_async16(&dB[br * SROWH + bg], B + (size_t)br * 256 + kk + bg, true);
            }
            CP_COMMIT();
            pa0 = va ? *(const float4*)(A + (size_t)(m0 + arow) * 256 + kk + acol)
                     : make_float4(0.f, 0.f, 0.f, 0.f);
            pa1 = va ? *(const float4*)(A + (size_t)(m0 + arow) * 256 + kk + acol + 4)
                     : make_float4(0.f, 0.f, 0.f, 0.f);
        }

        // compute chunk c
        const uint32_t ubA = (c & 1) ? uA1 : uA0;
        const uint32_t ubB = (c & 1) ? uB1 : uB0;
        #pragma unroll
        for (int ks = 0; ks < 2; ks++) {
            uint32_t af[2][4];
            #pragma unroll
            for (int mf = 0; mf < 2; mf++)
                ldmatrix_x4(af[mf], ubA + offA
                            + (uint32_t)(((wm + mf * 16) * SROWH + ks * 16) * 2));
            uint32_t bf[4][4];
            #pragma unroll
            for (int p = 0; p < 4; p++)
                ldmatrix_x4(bf[p], ubB + offB
                            + (uint32_t)(((wn + p * 16) * SROWH + ks * 16) * 2));
            #pragma unroll
            for (int mf = 0; mf < 2; mf++)
                #pragma unroll
                for (int nf = 0; nf < 8; nf++)
                    mma_f16_f32acc(acc[mf][nf], af[mf], bf[nf >> 1][(nf & 1) * 2],
                                   bf[nf >> 1][(nf & 1) * 2 + 1]);
        }

        // store prefetched A; await B; swap
        if (c < 7) {
            __half* dA = ((c + 1) & 1) ? sA1 : sA0;
            *(uint4*)&dA[arow * SROWH + acol] =
                make_uint4(pack_h2(pa0.x, pa0.y), pack_h2(pa0.z, pa0.w),
                           pack_h2(pa1.x, pa1.y), pack_h2(pa1.z, pa1.w));
            CP_WAIT0();
        }
        __syncthreads();
    }

    // ---- epilogue: relu + fp16 store (bias already in acc) ----
    #pragma unroll
    for (int mf = 0; mf < 2; mf++) {
        #pragma unroll
        for (int half = 0; half < 2; half++) {
            const int m = m0 + wm + mf * 16 + g + half * 8;
            if (m < M) {
                #pragma unroll
                for (int nf = 0; nf < 8; nf++) {
                    const int cc = wn + nf * 8 + tg * 2;
                    const float v0 = fmaxf(acc[mf][nf][half * 2 + 0], 0.f);
                    const float v1 = fmaxf(acc[mf][nf][half * 2 + 1], 0.f);
                    *(uint32_t*)(C + (size_t)m * 256 + cc) = pack_h2(v0, v1);
                }
            }
        }
    }
}

// ===========================================================================
// GEMM-C + fused L2 norm: out[m0..m0+63, :] =
//   normalize( relu( g_cat @ Ww^T + Wb ) ). K=512, full N=256 per CTA.
// 2-stage WAIT0 double buffer. Bias pre-loaded into accumulators. 8 warps of
// 32x64. Epilogue: relu in regs -> per-row sumsq (quad shfl + smem atomics)
// -> rsqrt -> single fp32 store. 313 CTAs, 51.5 KB dyn smem, 2 CTAs/SM.
// ===========================================================================
#define GC_SMEM ((2 * 64 * SROWH + 2 * 256 * SROWH) * 2 + 256)

__global__ __launch_bounds__(256, 2) void gemm_c_kernel(
    const __half* __restrict__ A, const __half* __restrict__ B,
    const float* __restrict__ bias, float* __restrict__ C, int M)
{
    extern __shared__ __half dsm[];
    __half* sA0 = dsm;
    __half* sA1 = dsm + 64 * SROWH;
    __half* sB0 = dsm + 2 * 64 * SROWH;
    __half* sB1 = sB0 + 256 * SROWH;
    float*  s_ss = (float*)(sB1 + 256 * SROWH);   // [64] per-row sumsq

    const int tid  = threadIdx.x;
    const int warp = tid >> 5;
    const int lane = tid & 31;
    const int g    = lane >> 2;
    const int tg   = lane & 3;
    const int m0   = (int)blockIdx.x * 64;
    const int wm   = (warp >> 2) * 32;
    const int wn   = (warp & 3) * 64;
    const int K    = 512;

    const int ar = tid >> 2, ag = (tid & 3) * 8;
    const bool va = (m0 + ar) < M;

    // accumulators initialized with bias
    float acc[2][8][4];
    #pragma unroll
    for (int nf = 0; nf < 8; nf++) {
        const int cc = wn + nf * 8 + tg * 2;
        const float b0 = __ldg(&bias[cc]);
        const float b1 = __ldg(&bias[cc + 1]);
        #pragma unroll
        for (int mf = 0; mf < 2; mf++) {
            acc[mf][nf][0] = b0; acc[mf][nf][1] = b1;
            acc[mf][nf][2] = b0; acc[mf][nf][3] = b1;
        }
    }

    if (tid < 64) s_ss[tid] = 0.f;

    // ---- prologue: async-stage chunk 0 ----
    cp_async16(&sA0[ar * SROWH + ag], A + (size_t)(m0 + ar) * K + ag, va);
    #pragma unroll
    for (int t = 0; t < 4; t++) {
        const int i  = tid + t * 256;
        const int br = i >> 2, bg = (i & 3) * 8;
        cp_async16(&sB0[br * SROWH + bg], B + (size_t)br * K + bg, true);
    }
    CP_COMMIT();
    CP_WAIT0();
    __syncthreads();

    const uint32_t uA0  = (uint32_t)__cvta_generic_to_shared(sA0);
    const uint32_t uA1  = (uint32_t)__cvta_generic_to_shared(sA1);
    const uint32_t uB0  = (uint32_t)__cvta_generic_to_shared(sB0);
    const uint32_t uB1  = (uint32_t)__cvta_generic_to_shared(sB1);
    const uint32_t offA = (uint32_t)(((lane & 15) * SROWH + (lane >> 4) * 8) * 2);
    const uint32_t offB = (uint32_t)((((lane >> 4) * 8 + (lane & 7)) * SROWH
                                      + ((lane >> 3) & 1) * 8) * 2);

    #pragma unroll 1
    for (int c = 0; c < 16; c++) {
        if (c < 15) {
            const int kk = (c + 1) * 32;
            __half* dA = ((c + 1) & 1) ? sA1 : sA0;
            __half* dB = ((c + 1) & 1) ? sB1 : sB0;
            cp_async16(&dA[ar * SROWH + ag], A + (size_t)(m0 + ar) * K + kk + ag, va);
            #pragma unroll
            for (int t = 0; t < 4; t++) {
                const int i  = tid + t * 256;
                const int br = i >> 2, bg = (i & 3) * 8;
                cp_async16(&dB[br * SROWH + bg], B + (size_t)br * K + kk + bg, true);
            }
            CP_COMMIT();
        }

        const uint32_t ubA = (c & 1) ? uA1 : uA0;
        const uint32_t ubB = (c & 1) ? uB1 : uB0;
        #pragma unroll
        for (int ks = 0; ks < 2; ks++) {
            uint32_t af[2][4];
            #pragma unroll
            for (int mf = 0; mf < 2; mf++)
                ldmatrix_x4(af[mf], ubA + offA
                            + (uint32_t)(((wm + mf * 16) * SROWH + ks * 16) * 2));
            uint32_t bf[4][4];
            #pragma unroll
            for (int p = 0; p < 4; p++)
                ldmatrix_x4(bf[p], ubB + offB
                            + (uint32_t)(((wn + p * 16) * SROWH + ks * 16) * 2));
            #pragma unroll
            for (int mf = 0; mf < 2; mf++)
                #pragma unroll
                for (int nf = 0; nf < 8; nf++)
                    mma_f16_f32acc(acc[mf][nf], af[mf], bf[nf >> 1][(nf & 1) * 2],
                                   bf[nf >> 1][(nf & 1) * 2 + 1]);
        }

        if (c < 15) CP_WAIT0();
        __syncthreads();
    }

    // ---- epilogue: relu in regs, fused per-row L2 norm, fp32 store ----
    float ss[2][2];
    #pragma unroll
    for (int mf = 0; mf < 2; mf++)
        #pragma unroll
        for (int half = 0; half < 2; half++) {
            float s = 0.f;
            #pragma unroll
            for (int nf = 0; nf < 8; nf++) {
                float v0 = fmaxf(acc[mf][nf][half * 2 + 0], 0.f);
                float v1 = fmaxf(acc[mf][nf][half * 2 + 1], 0.f);
                acc[mf][nf][half * 2 + 0] = v0;
                acc[mf][nf][half * 2 + 1] = v1;
                s += v0 * v0 + v1 * v1;
            }
            ss[mf][half] = s;
        }
    #pragma unroll
    for (int mf = 0; mf < 2; mf++)
        #pragma unroll
        for (int half = 0; half < 2; half++) {
            ss[mf][half] += __shfl_xor_sync(0xffffffffu, ss[mf][half], 1);
            ss[mf][half] += __shfl_xor_sync(0xffffffffu, ss[mf][half], 2);
        }
    if (tg == 0) {
        #pragma unroll
        for (int mf = 0; mf < 2; mf++)
            #pragma unroll
            for (int half = 0; half < 2; half++)
                atomicAdd(&s_ss[wm + mf * 16 + g + half * 8], ss[mf][half]);
    }
    __syncthreads();

    #pragma unroll
    for (int mf = 0; mf < 2; mf++)
        #pragma unroll
        for (int half = 0; half < 2; half++) {
            const int r = wm + mf * 16 + g + half * 8;
            const int m = m0 + r;
            if (m < M) {
                const float inv = rsqrtf(s_ss[r]);
                #pragma unroll
                for (int nf = 0; nf < 8; nf++) {
                    const int cc = wn + nf * 8 + tg * 2;
                    *(float2*)(C + (size_t)m * 256 + cc) =
                        make_float2(acc[mf][nf][half * 2 + 0] * inv,
                                    acc[mf][nf][half * 2 + 1] * inv);
                }
            }
        }
}

// ---------------------------------------------------------------------------
// Aggregation (R13-proven) + folded Ww fp32->fp16 conversion.
// h_agg[n] = sum_t w*QH[nb[n,t]] / sum_t w; QH fp16 (L2-resident, ~LTS cap).
// One warp per node; also copies h[nodeset[n]] (fp32->fp16) into the first
// half of the concat row. First 32768 threads additionally convert one
// float4 of Ww (ready before gemm_c by the kernel-boundary sync).
// ---------------------------------------------------------------------------
__global__ __launch_bounds__(256) void agg_kernel(
    const float* __restrict__ h, const int* __restrict__ nodeset,
    const int* __restrict__ nb_nodes, const float* __restrict__ nb_w,
    const float* __restrict__ Ww)
{
    __shared__ int   s_idx[8][TN];
    __shared__ float s_w[8][TN];

    const int tid  = threadIdx.x;
    const int warp = tid >> 5;
    const int lane = tid & 31;
    const int n    = blockIdx.x * 8 + warp;   // 2500 blocks exact

    // folded Ww conversion (32768 float4 total)
    const int wi = blockIdx.x * 256 + tid;
    if (wi < 32768) {
        const float4 v = ((const float4*)Ww)[wi];
        ((uint2*)g_ww16)[wi] = make_uint2(pack_h2(v.x, v.y), pack_h2(v.z, v.w));
    }

    for (int j = lane; j < TN; j += 32) {
        s_idx[warp][j] = nb_nodes[n * TN + j];
        s_w[warp][j]   = nb_w[n * TN + j];
    }
    __syncwarp();

    float wsum = 0.f;
    #pragma unroll
    for (int t = 0; t < TN; t++) wsum += s_w[warp][t];

    const int colb = lane * 8;
    float acc[8];
    #pragma unroll
    for (int i = 0; i < 8; i++) acc[i] = 0.f;

    #pragma unroll 10
    for (int t = 0; t < TN; t++) {
        const int   idx = s_idx[warp][t];
        const float w   = s_w[warp][t];
        union { uint4 u; __half2 h2[4]; } q;
        q.u = *(const uint4*)(g_qh + (size_t)idx * HIDF + colb);
        #pragma unroll
        for (int i = 0; i < 4; i++) {
            const float2 f = __half22float2(q.h2[i]);
            acc[2 * i]     += w * f.x;
            acc[2 * i + 1] += w * f.y;
        }
    }
    const float inv = 1.f / wsum;
    union { uint4 u; __half2 h2[4]; } o;
    #pragma unroll
    for (int i = 0; i < 4; i++)
        o.h2[i] = __float22half2_rn(make_float2(acc[2 * i] * inv, acc[2 * i + 1] * inv));
    *(uint4*)(g_cat + (size_t)n * CATF + INF + colb) = o.u;

    const int self = nodeset[n];
    const float4 s0 = *(const float4*)(h + (size_t)self * INF + colb);
    const float4 s1 = *(const float4*)(h + (size_t)self * INF + colb + 4);
    union { uint4 u; __half2 h2[4]; } sc;
    sc.h2[0] = __float22half2_rn(make_float2(s0.x, s0.y));
    sc.h2[1] = __float22half2_rn(make_float2(s0.z, s0.w));
    sc.h2[2] = __float22half2_rn(make_float2(s1.x, s1.y));
    sc.h2[3] = __float22half2_rn(make_float2(s1.z, s1.w));
    *(uint4*)(g_cat + (size_t)n * CATF + colb) = sc.u;
}

// ---------------------------------------------------------------------------
extern "C" void kernel_launch(void* const* d_in, const int* in_sizes, int n_in,
                              void* d_out, int out_size)
{
    const float* h        = (const float*)d_in[0];
    const int*   nodeset  = (const int*)d_in[1];
    const int*   nb_nodes = (const int*)d_in[2];
    const float* nb_w     = (const float*)d_in[3];
    const float* Qw       = (const float*)d_in[4];
    const float* Qb       = (const float*)d_in[5];
    const float* Ww       = (const float*)d_in[6];
    const float* Wb       = (const float*)d_in[7];
    float*       out      = (float*)d_out;

    __half* qh   = nullptr;
    __half* cat  = nullptr;
    __half* qw16 = nullptr;
    __half* ww16 = nullptr;
    cudaGetSymbolAddress((void**)&qh,   g_qh);
    cudaGetSymbolAddress((void**)&cat,  g_cat);
    cudaGetSymbolAddress((void**)&qw16, g_qw16);
    cudaGetSymbolAddress((void**)&ww16, g_ww16);

    static bool attr_done = false;
    if (!attr_done) {
        cudaFuncSetAttribute(gemm_a_kernel,
                             cudaFuncAttributeMaxDynamicSharedMemorySize, GA_SMEM);
        cudaFuncSetAttribute(gemm_c_kernel,
                             cudaFuncAttributeMaxDynamicSharedMemorySize, GC_SMEM);
        attr_done = true;
    }

    // k0: Qw -> fp16 (Ww conversion rides inside the agg kernel)
    cvt_qw_kernel<<<64, 256>>>(Qw);

    // k1: QH = relu(h @ Qw^T + Qb) -> fp16 [100000, 256]
    {
        const int tilesM = (NODES_TOTAL + 63) / 64;   // 1563
        gemm_a_kernel<<<tilesM, 256, GA_SMEM>>>(h, qw16, Qb, qh, NODES_TOTAL);
    }
    // k2: aggregate + self gather -> g_cat fp16 [20000, 512]  (+ Ww cvt)
    agg_kernel<<<NNODES / 8, 256>>>(h, nodeset, nb_nodes, nb_w, Ww);

    // k3: out = normalize(relu(g_cat @ Ww^T + Wb))  [20000, 256] (norm fused)
    {
        const int tilesM = (NNODES + 63) / 64;        // 313
        gemm_c_kernel<<<tilesM, 256, GC_SMEM>>>(cat, ww16, Wb, out, NNODES);
    }
}